// round 6
// baseline (speedup 1.0000x reference)
#include <cuda_runtime.h>
#include <cuda_bf16.h>
#include <math.h>

// Problem constants
#define BB   4
#define SS   1024
#define DIN  256
#define VV   256
#define KDIM 64
#define HH   8
#define TT   4
#define BS   (BB*SS)          // 4096
#define NCH  32               // row chunks for BN stats (4096/128)
#define EPS  1e-3f

// ---------------- scratch (device globals; no allocation allowed) -----------
__device__ float g_net[HH*BS*VV];
__device__ float g_q[HH*BS*KDIM];
__device__ float g_k[HH*BS*KDIM];
__device__ float g_v[HH*BS*VV];
__device__ float g_attnout[HH*BS*VV];
__device__ float g_z[HH*BS*VV];
__device__ float g_part[HH*NCH*VV*2];

// ---------------- TF32 helpers ----------------------------------------------
__device__ __forceinline__ unsigned f2tf(float f) {
    unsigned r;
    asm("cvt.rna.tf32.f32 %0, %1;" : "=r"(r) : "f"(f));
    return r;
}

__device__ __forceinline__ void split_tf32(float f, unsigned &hi, unsigned &lo) {
    hi = f2tf(f);
    lo = f2tf(f - __uint_as_float(hi));
}

__device__ __forceinline__ void mma_tf32(float c[4],
                                         const unsigned a[4],
                                         const unsigned b[2]) {
    asm volatile(
        "mma.sync.aligned.m16n8k8.row.col.f32.tf32.tf32.f32 "
        "{%0,%1,%2,%3}, {%4,%5,%6,%7}, {%8,%9}, {%0,%1,%2,%3};"
        : "+f"(c[0]), "+f"(c[1]), "+f"(c[2]), "+f"(c[3])
        : "r"(a[0]), "r"(a[1]), "r"(a[2]), "r"(a[3]), "r"(b[0]), "r"(b[1]));
}

// ---------------- 3xTF32 tensor-core GEMM (dense layers) ---------------------
#define GBM 128
#define GBN 64
#define GBK 32
#define ASTR 36
#define BSTR_NN 72
#define A_TILE (GBM*ASTR)
#define B_TILE 2304
#define SMEM_U32 (2*A_TILE + 2*B_TILE)   // 13824 u32 = 55296 B

__global__ void __launch_bounds__(256)
gemm_mma(const float* __restrict__ A, const float* __restrict__ B,
         float* __restrict__ C, int M, int N, int K,
         long long sA, long long sB, long long sC,
         float alpha, int rep, long long repStride)
{
    A += (long long)blockIdx.z * sA;
    B += (long long)blockIdx.z * sB;
    C += (long long)blockIdx.z * sC;

    extern __shared__ unsigned smem[];
    unsigned* AsH = smem;
    unsigned* AsL = smem + A_TILE;
    unsigned* BsH = smem + 2*A_TILE;
    unsigned* BsL = smem + 2*A_TILE + B_TILE;

    const int t    = threadIdx.x;
    const int lane = t & 31;
    const int wid  = t >> 5;
    const int gid  = lane >> 2;
    const int tig  = lane & 3;
    const int wm   = (wid & 3) * 32;
    const int wn   = (wid >> 2) * 32;
    const int m0 = blockIdx.y * GBM, n0 = blockIdx.x * GBN;

    float acc[2][4][4] = {};

    for (int k0 = 0; k0 < K; k0 += GBK) {
        float4 ar[4];
        #pragma unroll
        for (int i = 0; i < 4; i++) {
            int idx = t + i * 256;
            int r = idx >> 3, c4 = (idx & 7) << 2;
            ar[i] = *(const float4*)&A[(size_t)(m0 + r) * K + k0 + c4];
        }
        float4 br[2];
        #pragma unroll
        for (int i = 0; i < 2; i++) {
            int idx = t + i * 256;
            int r = idx >> 4, c4 = (idx & 15) << 2;
            br[i] = *(const float4*)&B[(size_t)(k0 + r) * N + n0 + c4];
        }
        __syncthreads();
        #pragma unroll
        for (int i = 0; i < 4; i++) {
            int idx = t + i * 256;
            int r = idx >> 3, c4 = (idx & 7) << 2;
            unsigned* ph = &AsH[r * ASTR + c4];
            unsigned* pl = &AsL[r * ASTR + c4];
            split_tf32(ar[i].x, ph[0], pl[0]);
            split_tf32(ar[i].y, ph[1], pl[1]);
            split_tf32(ar[i].z, ph[2], pl[2]);
            split_tf32(ar[i].w, ph[3], pl[3]);
        }
        #pragma unroll
        for (int i = 0; i < 2; i++) {
            int idx = t + i * 256;
            int r = idx >> 4, c4 = (idx & 15) << 2;
            int off = r * BSTR_NN + c4;
            unsigned* ph = &BsH[off];
            unsigned* pl = &BsL[off];
            split_tf32(br[i].x, ph[0], pl[0]);
            split_tf32(br[i].y, ph[1], pl[1]);
            split_tf32(br[i].z, ph[2], pl[2]);
            split_tf32(br[i].w, ph[3], pl[3]);
        }
        __syncthreads();

        #pragma unroll
        for (int ks = 0; ks < 4; ks++) {
            const int kk = ks * 8;
            unsigned aH[2][4], aL[2][4];
            #pragma unroll
            for (int i = 0; i < 2; i++) {
                const int mr = wm + i * 16;
                const int o0 = (mr + gid    ) * ASTR + kk + tig;
                const int o1 = (mr + gid + 8) * ASTR + kk + tig;
                aH[i][0] = AsH[o0];     aL[i][0] = AsL[o0];
                aH[i][1] = AsH[o1];     aL[i][1] = AsL[o1];
                aH[i][2] = AsH[o0 + 4]; aL[i][2] = AsL[o0 + 4];
                aH[i][3] = AsH[o1 + 4]; aL[i][3] = AsL[o1 + 4];
            }
            unsigned bH[4][2], bL[4][2];
            #pragma unroll
            for (int j = 0; j < 4; j++) {
                const int nc = wn + j * 8 + gid;
                int o0 = (kk + tig) * BSTR_NN + nc;
                int o1 = o0 + 4 * BSTR_NN;
                bH[j][0] = BsH[o0]; bL[j][0] = BsL[o0];
                bH[j][1] = BsH[o1]; bL[j][1] = BsL[o1];
            }
            #pragma unroll
            for (int i = 0; i < 2; i++)
                #pragma unroll
                for (int j = 0; j < 4; j++) {
                    mma_tf32(acc[i][j], aL[i], bH[j]);
                    mma_tf32(acc[i][j], aH[i], bL[j]);
                    mma_tf32(acc[i][j], aH[i], bH[j]);
                }
        }
        __syncthreads();
    }

    #pragma unroll
    for (int i = 0; i < 2; i++)
        #pragma unroll
        for (int j = 0; j < 4; j++) {
            const int r0 = m0 + wm + i * 16 + gid;
            const int c0 = n0 + wn + j * 8 + tig * 2;
            float2 v01 = make_float2(acc[i][j][0] * alpha, acc[i][j][1] * alpha);
            float2 v23 = make_float2(acc[i][j][2] * alpha, acc[i][j][3] * alpha);
            for (int r = 0; r < rep; r++) {
                *(float2*)&C[(size_t)r0 * N + c0 + (size_t)r * repStride] = v01;
                *(float2*)&C[(size_t)(r0 + 8) * N + c0 + (size_t)r * repStride] = v23;
            }
        }
}

// ---------------- fused flash attention (3xTF32) -----------------------------
// Per CTA: 64 q-rows of one (h,b); loop over 16 key chunks of 64.
// S warp grid: 4m x 2n (warp 16x32). O warp grid: 4m x 2n (warp 16x128).
#define FQT 64
#define FTC 64
#define FSTR 68
// smem u32 offsets
#define SQH 0
#define SQL 4352
#define SKH 8704
#define SKL 13056
#define SPH 17408
#define SPL 21760
#define SVT 26112          // 256*68 floats
#define SPMAX 43520        // 128 floats
#define SPSUM 43648        // 128 floats
#define FSMEM_U32 43776    // 175104 bytes

__global__ void __launch_bounds__(256)
attn_flash(const float* __restrict__ Q, const float* __restrict__ K,
           const float* __restrict__ V, float* __restrict__ O)
{
    extern __shared__ unsigned sm[];
    unsigned *Qh = sm + SQH, *Ql = sm + SQL;
    unsigned *Kh = sm + SKH, *Kl = sm + SKL;
    unsigned *Ph = sm + SPH, *Pl = sm + SPL;
    float *Vt   = (float*)(sm + SVT);
    float *pmax = (float*)(sm + SPMAX);
    float *psum = (float*)(sm + SPSUM);

    const int t = threadIdx.x, lane = t & 31, wid = t >> 5;
    const int gid = lane >> 2, tig = lane & 3;
    const int wm = (wid & 3) * 16;      // warp row offset
    const int wc = wid >> 2;            // warp col (0/1)
    const int wnS = wc * 32;
    const int wnO = wc * 128;
    const int bh = blockIdx.y;          // h*BB + b
    const int h = bh >> 2, b = bh & 3;
    const int q0 = blockIdx.x * FQT;
    const float scale = 0.125f;

    const float* Qb = Q + (size_t)(h*BS + b*SS + q0) * KDIM;
    const float* Kb = K + (size_t)(h*BS + b*SS) * KDIM;
    const float* Vb = V + (size_t)(h*BS + b*SS) * VV;
    float*       Ob = O + (size_t)(h*BS + b*SS + q0) * VV;

    // ---- load Q tile once ----
    #pragma unroll
    for (int i = 0; i < 4; i++) {
        int idx = t + i * 256;               // 1024 float4
        int r = idx >> 4, c4 = (idx & 15) << 2;
        float4 f = *(const float4*)&Qb[(size_t)r * KDIM + c4];
        unsigned* ph = &Qh[r * FSTR + c4];
        unsigned* pl = &Ql[r * FSTR + c4];
        split_tf32(f.x, ph[0], pl[0]);
        split_tf32(f.y, ph[1], pl[1]);
        split_tf32(f.z, ph[2], pl[2]);
        split_tf32(f.w, ph[3], pl[3]);
    }

    float oacc[16][4] = {};
    float m0r = -INFINITY, m1r = -INFINITY;
    float l0 = 0.f, l1 = 0.f;

    for (int kc = 0; kc < SS / FTC; kc++) {
        const int k0 = kc * FTC;
        // ---- fill K chunk (split) ----
        #pragma unroll
        for (int i = 0; i < 4; i++) {
            int idx = t + i * 256;
            int r = idx >> 4, c4 = (idx & 15) << 2;
            float4 f = *(const float4*)&Kb[(size_t)(k0 + r) * KDIM + c4];
            unsigned* ph = &Kh[r * FSTR + c4];
            unsigned* pl = &Kl[r * FSTR + c4];
            split_tf32(f.x, ph[0], pl[0]);
            split_tf32(f.y, ph[1], pl[1]);
            split_tf32(f.z, ph[2], pl[2]);
            split_tf32(f.w, ph[3], pl[3]);
        }
        // ---- fill V chunk transposed, fp32 ----
        #pragma unroll
        for (int i = 0; i < 16; i++) {
            int idx = t + i * 256;               // 4096 float4
            int kr = idx >> 6, n4 = (idx & 63) << 2;
            float4 f = *(const float4*)&Vb[(size_t)(k0 + kr) * VV + n4];
            Vt[(n4 + 0) * FSTR + kr] = f.x;
            Vt[(n4 + 1) * FSTR + kr] = f.y;
            Vt[(n4 + 2) * FSTR + kr] = f.z;
            Vt[(n4 + 3) * FSTR + kr] = f.w;
        }
        __syncthreads();

        // ---- S = Q @ K^T (3xTF32), warp tile 16x32 ----
        float facc[4][4] = {};
        #pragma unroll
        for (int ks = 0; ks < 8; ks++) {
            const int kk = ks * 8;
            unsigned aH[4], aL[4];
            const int o0 = (wm + gid) * FSTR + kk + tig;
            const int o1 = o0 + 8 * FSTR;
            aH[0] = Qh[o0];     aL[0] = Ql[o0];
            aH[1] = Qh[o1];     aL[1] = Ql[o1];
            aH[2] = Qh[o0 + 4]; aL[2] = Ql[o0 + 4];
            aH[3] = Qh[o1 + 4]; aL[3] = Ql[o1 + 4];
            #pragma unroll
            for (int j = 0; j < 4; j++) {
                const int nc = wnS + j * 8 + gid;
                const int ob = nc * FSTR + kk + tig;
                unsigned bH[2] = { Kh[ob], Kh[ob + 4] };
                unsigned bL[2] = { Kl[ob], Kl[ob + 4] };
                mma_tf32(facc[j], aL, bH);
                mma_tf32(facc[j], aH, bL);
                mma_tf32(facc[j], aH, bH);
            }
        }
        // scale
        #pragma unroll
        for (int j = 0; j < 4; j++)
            #pragma unroll
            for (int e = 0; e < 4; e++) facc[j][e] *= scale;

        // ---- online softmax: partial row max ----
        float ml0 = -INFINITY, ml1 = -INFINITY;
        #pragma unroll
        for (int j = 0; j < 4; j++) {
            ml0 = fmaxf(ml0, fmaxf(facc[j][0], facc[j][1]));
            ml1 = fmaxf(ml1, fmaxf(facc[j][2], facc[j][3]));
        }
        ml0 = fmaxf(ml0, __shfl_xor_sync(0xffffffffu, ml0, 1));
        ml0 = fmaxf(ml0, __shfl_xor_sync(0xffffffffu, ml0, 2));
        ml1 = fmaxf(ml1, __shfl_xor_sync(0xffffffffu, ml1, 1));
        ml1 = fmaxf(ml1, __shfl_xor_sync(0xffffffffu, ml1, 2));
        if (tig == 0) {
            pmax[wc * 64 + wm + gid]     = ml0;
            pmax[wc * 64 + wm + 8 + gid] = ml1;
        }
        __syncthreads();

        const float nm0 = fmaxf(m0r, fmaxf(pmax[wm + gid],     pmax[64 + wm + gid]));
        const float nm1 = fmaxf(m1r, fmaxf(pmax[wm + 8 + gid], pmax[64 + wm + 8 + gid]));
        const float al0 = __expf(m0r - nm0);
        const float al1 = __expf(m1r - nm1);

        // ---- P = exp(S - m); store hi/lo; partial sums ----
        float s0 = 0.f, s1 = 0.f;
        #pragma unroll
        for (int j = 0; j < 4; j++) {
            const int col = wnS + j * 8 + tig * 2;
            float p00 = __expf(facc[j][0] - nm0);
            float p01 = __expf(facc[j][1] - nm0);
            float p10 = __expf(facc[j][2] - nm1);
            float p11 = __expf(facc[j][3] - nm1);
            s0 += p00 + p01;
            s1 += p10 + p11;
            const int r0o = (wm + gid) * FSTR + col;
            const int r1o = (wm + 8 + gid) * FSTR + col;
            split_tf32(p00, Ph[r0o],     Pl[r0o]);
            split_tf32(p01, Ph[r0o + 1], Pl[r0o + 1]);
            split_tf32(p10, Ph[r1o],     Pl[r1o]);
            split_tf32(p11, Ph[r1o + 1], Pl[r1o + 1]);
        }
        s0 += __shfl_xor_sync(0xffffffffu, s0, 1);
        s0 += __shfl_xor_sync(0xffffffffu, s0, 2);
        s1 += __shfl_xor_sync(0xffffffffu, s1, 1);
        s1 += __shfl_xor_sync(0xffffffffu, s1, 2);
        if (tig == 0) {
            psum[wc * 64 + wm + gid]     = s0;
            psum[wc * 64 + wm + 8 + gid] = s1;
        }
        __syncthreads();

        const float rs0 = psum[wm + gid]     + psum[64 + wm + gid];
        const float rs1 = psum[wm + 8 + gid] + psum[64 + wm + 8 + gid];
        l0 = l0 * al0 + rs0;
        l1 = l1 * al1 + rs1;
        m0r = nm0; m1r = nm1;

        // ---- rescale O acc ----
        #pragma unroll
        for (int j = 0; j < 16; j++) {
            oacc[j][0] *= al0; oacc[j][1] *= al0;
            oacc[j][2] *= al1; oacc[j][3] *= al1;
        }

        // ---- O += P @ V (3xTF32), warp tile 16x128, V split on load ----
        #pragma unroll
        for (int ks = 0; ks < 8; ks++) {
            const int kk = ks * 8;
            unsigned aH[4], aL[4];
            const int o0 = (wm + gid) * FSTR + kk + tig;
            const int o1 = o0 + 8 * FSTR;
            aH[0] = Ph[o0];     aL[0] = Pl[o0];
            aH[1] = Ph[o1];     aL[1] = Pl[o1];
            aH[2] = Ph[o0 + 4]; aL[2] = Pl[o0 + 4];
            aH[3] = Ph[o1 + 4]; aL[3] = Pl[o1 + 4];
            #pragma unroll
            for (int j = 0; j < 16; j++) {
                const int nc = wnO + j * 8 + gid;
                const int ob = nc * FSTR + kk + tig;
                float b0 = Vt[ob], b1 = Vt[ob + 4];
                unsigned bH[2], bL[2];
                split_tf32(b0, bH[0], bL[0]);
                split_tf32(b1, bH[1], bL[1]);
                mma_tf32(oacc[j], aL, bH);
                mma_tf32(oacc[j], aH, bL);
                mma_tf32(oacc[j], aH, bH);
            }
        }
        __syncthreads();
    }

    // ---- epilogue: divide by l, store ----
    const float inv0 = 1.f / l0, inv1 = 1.f / l1;
    #pragma unroll
    for (int j = 0; j < 16; j++) {
        const int c = wnO + j * 8 + tig * 2;
        const int r = wm + gid;
        *(float2*)&Ob[(size_t)r * VV + c] =
            make_float2(oacc[j][0] * inv0, oacc[j][1] * inv0);
        *(float2*)&Ob[(size_t)(r + 8) * VV + c] =
            make_float2(oacc[j][2] * inv1, oacc[j][3] * inv1);
    }
}

// ---------------- y = a + (relu?)(b); partial column stats -------------------
__global__ void add_stats(const float* __restrict__ a, const float* __restrict__ b,
                          float* __restrict__ y, float* __restrict__ part, int relu)
{
    const int c = threadIdx.x;
    const int h = blockIdx.y;
    const int chunk = blockIdx.x;
    const size_t base = (size_t)h * BS * VV;
    float sum = 0.f, sq = 0.f;
    const int r0 = chunk * 128;
    for (int r = r0; r < r0 + 128; r++) {
        size_t idx = base + (size_t)r * VV + c;
        float bv = b[idx];
        if (relu) bv = fmaxf(bv, 0.f);
        float yv = a[idx] + bv;
        y[idx] = yv;
        sum += yv; sq += yv * yv;
    }
    size_t p = ((size_t)(h*NCH + chunk)*VV + c) * 2;
    part[p + 0] = sum;
    part[p + 1] = sq;
}

// ---------------- batchnorm normalize ---------------------------------------
__global__ void bn_norm(float* __restrict__ y, const float* __restrict__ part,
                        const float* __restrict__ gamma, const float* __restrict__ beta,
                        int gstride)
{
    const int c = threadIdx.x;
    const int h = blockIdx.y;
    const int chunk = blockIdx.x;
    const float* p = part + (size_t)h * NCH * VV * 2;
    float sum = 0.f, sq = 0.f;
    #pragma unroll
    for (int j = 0; j < NCH; j++) {
        sum += p[((size_t)j*VV + c)*2 + 0];
        sq  += p[((size_t)j*VV + c)*2 + 1];
    }
    const float mean = sum * (1.f / BS);
    const float var  = sq  * (1.f / BS) - mean * mean;
    const float inv  = rsqrtf(var + EPS);
    const float g = gamma[(size_t)h * gstride + c];
    const float b = beta [(size_t)h * gstride + c];
    const float sc = inv * g;
    const float sh = b - mean * sc;
    float* base = y + (size_t)h * BS * VV;
    const int r0 = chunk * 128;
    for (int r = r0; r < r0 + 128; r++) {
        size_t idx = (size_t)r * VV + c;
        base[idx] = base[idx] * sc + sh;
    }
}

// ---------------- [H][B*S][V] -> [B,S,H,V] -----------------------------------
__global__ void write_out(const float* __restrict__ net, float* __restrict__ out)
{
    const int h = blockIdx.y, row = blockIdx.x, c = threadIdx.x;
    out[((size_t)row * HH + h) * VV + c] =
        net[(size_t)h * BS * VV + (size_t)row * VV + c];
}

// ---------------- launcher ---------------------------------------------------
extern "C" void kernel_launch(void* const* d_in, const int* in_sizes, int n_in,
                              void* d_out, int out_size)
{
    const float* x     = (const float*)d_in[0];
    const float* W_in  = (const float*)d_in[1];
    const float* Wq    = (const float*)d_in[2];
    const float* Wk    = (const float*)d_in[3];
    const float* Wv    = (const float*)d_in[4];
    const float* Wd    = (const float*)d_in[5];
    const float* g1    = (const float*)d_in[6];
    const float* b1    = (const float*)d_in[7];
    const float* g2    = (const float*)d_in[8];
    const float* b2    = (const float*)d_in[9];
    float* out = (float*)d_out;

    float *net, *q, *k, *v, *attnout, *z, *part;
    cudaGetSymbolAddress((void**)&net,     g_net);
    cudaGetSymbolAddress((void**)&q,       g_q);
    cudaGetSymbolAddress((void**)&k,       g_k);
    cudaGetSymbolAddress((void**)&v,       g_v);
    cudaGetSymbolAddress((void**)&attnout, g_attnout);
    cudaGetSymbolAddress((void**)&z,       g_z);
    cudaGetSymbolAddress((void**)&part,    g_part);

    const int smem_bytes  = SMEM_U32 * 4;    // 55296
    const int fsmem_bytes = FSMEM_U32 * 4;   // 175104
    static int configured = 0;
    if (!configured) {
        cudaFuncSetAttribute(gemm_mma,   cudaFuncAttributeMaxDynamicSharedMemorySize, smem_bytes);
        cudaFuncSetAttribute(attn_flash, cudaFuncAttributeMaxDynamicSharedMemorySize, fsmem_bytes);
        configured = 1;
    }

    // net[h] = x @ W_in, replicated to all 8 heads
    gemm_mma<<<dim3(VV/GBN, BS/GBM, 1), 256, smem_bytes>>>(x, W_in, net, BS, VV, DIN,
                                                  0, 0, 0, 1.f, HH, (long long)BS*VV);

    for (int t = 0; t < TT; t++) {
        gemm_mma<<<dim3(KDIM/GBN, BS/GBM, HH), 256, smem_bytes>>>(net, Wq + (size_t)t*VV*KDIM, q,
            BS, KDIM, VV, (long long)BS*VV, (long long)TT*VV*KDIM, (long long)BS*KDIM, 1.f, 1, 0);
        gemm_mma<<<dim3(KDIM/GBN, BS/GBM, HH), 256, smem_bytes>>>(net, Wk + (size_t)t*VV*KDIM, k,
            BS, KDIM, VV, (long long)BS*VV, (long long)TT*VV*KDIM, (long long)BS*KDIM, 1.f, 1, 0);
        gemm_mma<<<dim3(VV/GBN, BS/GBM, HH), 256, smem_bytes>>>(net, Wv + (size_t)t*VV*VV, v,
            BS, VV, VV, (long long)BS*VV, (long long)TT*VV*VV, (long long)BS*VV, 1.f, 1, 0);

        // fused attention: scores + softmax + P@V
        attn_flash<<<dim3(SS/FQT, HH*BB), 256, fsmem_bytes>>>(q, k, v, attnout);

        // net = BN(net + attnout)
        add_stats<<<dim3(NCH, HH), 256>>>(net, attnout, net, part, 0);
        bn_norm<<<dim3(NCH, HH), 256>>>(net, part, g1 + (size_t)t*VV, b1 + (size_t)t*VV, TT*VV);

        // z = net @ Wd; net = BN(net + relu(z))
        gemm_mma<<<dim3(VV/GBN, BS/GBM, HH), 256, smem_bytes>>>(net, Wd + (size_t)t*VV*VV, z,
            BS, VV, VV, (long long)BS*VV, (long long)TT*VV*VV, (long long)BS*VV, 1.f, 1, 0);
        add_stats<<<dim3(NCH, HH), 256>>>(net, z, net, part, 1);
        bn_norm<<<dim3(NCH, HH), 256>>>(net, part, g2 + (size_t)t*VV, b2 + (size_t)t*VV, TT*VV);
    }

    write_out<<<dim3(BS, HH), 256>>>(net, out);
}

// round 7
// speedup vs baseline: 1.4129x; 1.4129x over previous
#include <cuda_runtime.h>
#include <cuda_bf16.h>
#include <math.h>

// Problem constants
#define BB   4
#define SS   1024
#define DIN  256
#define VV   256
#define KDIM 64
#define HH   8
#define TT   4
#define BS   (BB*SS)          // 4096
#define NCH  32               // row chunks for BN stats (4096/128)
#define EPS  1e-3f

// ---------------- scratch (device globals; no allocation allowed) -----------
__device__ float g_net[HH*BS*VV];
__device__ float g_q[HH*BS*KDIM];
__device__ float g_k[HH*BS*KDIM];
__device__ float g_v[HH*BS*VV];
__device__ float g_scores[(size_t)HH*BB*SS*SS];  // 134MB
__device__ float g_attnout[HH*BS*VV];
__device__ float g_z[HH*BS*VV];
__device__ float g_part[HH*NCH*VV*2];

// ---------------- TF32 helpers ----------------------------------------------
__device__ __forceinline__ unsigned f2tf(float f) {
    unsigned r;
    asm("cvt.rna.tf32.f32 %0, %1;" : "=r"(r) : "f"(f));
    return r;
}

__device__ __forceinline__ void split_tf32(float f, unsigned &hi, unsigned &lo) {
    hi = f2tf(f);
    lo = f2tf(f - __uint_as_float(hi));
}

__device__ __forceinline__ void mma_tf32(float c[4],
                                         const unsigned a[4],
                                         const unsigned b[2]) {
    asm volatile(
        "mma.sync.aligned.m16n8k8.row.col.f32.tf32.tf32.f32 "
        "{%0,%1,%2,%3}, {%4,%5,%6,%7}, {%8,%9}, {%0,%1,%2,%3};"
        : "+f"(c[0]), "+f"(c[1]), "+f"(c[2]), "+f"(c[3])
        : "r"(a[0]), "r"(a[1]), "r"(a[2]), "r"(a[3]), "r"(b[0]), "r"(b[1]));
}

// ---------------- 3xTF32 tensor-core GEMM, C = alpha * A @ op(B) -------------
// BM=128, BN=64, BK=32; 256 threads, 8 warps (4m x 2n), warp tile 32x32.
// Double-buffered smem pipeline: next tile's LDGs issued before current MMAs.
// NT=0: B is [K,N] row-major (C = A@B).  NT=1: B is [N,K] row-major (C = A@B^T).
#define GBM 128
#define GBN 64
#define GBK 32
#define ASTR 36        // A smem row stride (u32)
#define BSTR_NN 72
#define BSTR_NT 36
#define A_TILE (GBM*ASTR)   // 4608 u32
#define B_TILE 2304         // u32
#define BUF_U32 (2*A_TILE + 2*B_TILE)    // 13824 u32 per buffer
#define SMEM_U32 (2*BUF_U32)             // 27648 u32 = 110592 B

template<int NT>
__global__ void __launch_bounds__(256)
gemm_mma(const float* __restrict__ A, const float* __restrict__ B,
         float* __restrict__ C, int M, int N, int K,
         long long sA, long long sB, long long sC,
         float alpha, int rep, long long repStride)
{
    A += (long long)blockIdx.z * sA;
    B += (long long)blockIdx.z * sB;
    C += (long long)blockIdx.z * sC;

    extern __shared__ unsigned smem[];

    const int t    = threadIdx.x;
    const int lane = t & 31;
    const int wid  = t >> 5;
    const int gid  = lane >> 2;
    const int tig  = lane & 3;
    const int wm   = (wid & 3) * 32;
    const int wn   = (wid >> 2) * 32;
    const int m0 = blockIdx.y * GBM, n0 = blockIdx.x * GBN;

    float acc[2][4][4] = {};
    float4 ar[4], br[2];

    // ---- G->R loader ----
    auto load_G = [&](int k0) {
        #pragma unroll
        for (int i = 0; i < 4; i++) {
            int idx = t + i * 256;
            int r = idx >> 3, c4 = (idx & 7) << 2;
            ar[i] = *(const float4*)&A[(size_t)(m0 + r) * K + k0 + c4];
        }
        #pragma unroll
        for (int i = 0; i < 2; i++) {
            int idx = t + i * 256;
            if (NT) {
                int r = idx >> 3, c4 = (idx & 7) << 2;
                br[i] = *(const float4*)&B[(size_t)(n0 + r) * K + k0 + c4];
            } else {
                int r = idx >> 4, c4 = (idx & 15) << 2;
                br[i] = *(const float4*)&B[(size_t)(k0 + r) * N + n0 + c4];
            }
        }
    };

    // ---- R->S split store ----
    auto store_S = [&](int buf) {
        unsigned* AsH = smem + buf * BUF_U32;
        unsigned* AsL = AsH + A_TILE;
        unsigned* BsH = AsH + 2*A_TILE;
        unsigned* BsL = AsH + 2*A_TILE + B_TILE;
        #pragma unroll
        for (int i = 0; i < 4; i++) {
            int idx = t + i * 256;
            int r = idx >> 3, c4 = (idx & 7) << 2;
            unsigned* ph = &AsH[r * ASTR + c4];
            unsigned* pl = &AsL[r * ASTR + c4];
            split_tf32(ar[i].x, ph[0], pl[0]);
            split_tf32(ar[i].y, ph[1], pl[1]);
            split_tf32(ar[i].z, ph[2], pl[2]);
            split_tf32(ar[i].w, ph[3], pl[3]);
        }
        #pragma unroll
        for (int i = 0; i < 2; i++) {
            int idx = t + i * 256;
            int off;
            if (NT) { int r = idx >> 3, c4 = (idx & 7) << 2;  off = r * BSTR_NT + c4; }
            else    { int r = idx >> 4, c4 = (idx & 15) << 2; off = r * BSTR_NN + c4; }
            unsigned* ph = &BsH[off];
            unsigned* pl = &BsL[off];
            split_tf32(br[i].x, ph[0], pl[0]);
            split_tf32(br[i].y, ph[1], pl[1]);
            split_tf32(br[i].z, ph[2], pl[2]);
            split_tf32(br[i].w, ph[3], pl[3]);
        }
    };

    // ---- MMA phase over one buffer ----
    auto mma_buf = [&](int buf) {
        unsigned* AsH = smem + buf * BUF_U32;
        unsigned* AsL = AsH + A_TILE;
        unsigned* BsH = AsH + 2*A_TILE;
        unsigned* BsL = AsH + 2*A_TILE + B_TILE;
        #pragma unroll
        for (int ks = 0; ks < 4; ks++) {
            const int kk = ks * 8;
            unsigned aH[2][4], aL[2][4];
            #pragma unroll
            for (int i = 0; i < 2; i++) {
                const int mr = wm + i * 16;
                const int o0 = (mr + gid    ) * ASTR + kk + tig;
                const int o1 = (mr + gid + 8) * ASTR + kk + tig;
                aH[i][0] = AsH[o0];     aL[i][0] = AsL[o0];
                aH[i][1] = AsH[o1];     aL[i][1] = AsL[o1];
                aH[i][2] = AsH[o0 + 4]; aL[i][2] = AsL[o0 + 4];
                aH[i][3] = AsH[o1 + 4]; aL[i][3] = AsL[o1 + 4];
            }
            unsigned bH[4][2], bL[4][2];
            #pragma unroll
            for (int j = 0; j < 4; j++) {
                const int nc = wn + j * 8 + gid;
                int o0, o1;
                if (NT) { o0 = nc * BSTR_NT + kk + tig;  o1 = o0 + 4; }
                else    { o0 = (kk + tig) * BSTR_NN + nc; o1 = o0 + 4 * BSTR_NN; }
                bH[j][0] = BsH[o0]; bL[j][0] = BsL[o0];
                bH[j][1] = BsH[o1]; bL[j][1] = BsL[o1];
            }
            #pragma unroll
            for (int i = 0; i < 2; i++)
                #pragma unroll
                for (int j = 0; j < 4; j++) {
                    mma_tf32(acc[i][j], aL[i], bH[j]);
                    mma_tf32(acc[i][j], aH[i], bL[j]);
                    mma_tf32(acc[i][j], aH[i], bH[j]);
                }
        }
    };

    // ---- pipelined main loop ----
    const int nIter = K / GBK;
    load_G(0);
    store_S(0);
    __syncthreads();
    for (int i = 0; i < nIter; i++) {
        if (i + 1 < nIter) load_G((i + 1) * GBK);   // LDGs in flight over MMAs
        mma_buf(i & 1);
        if (i + 1 < nIter) store_S((i + 1) & 1);
        __syncthreads();
    }

    // ---- epilogue ----
    #pragma unroll
    for (int i = 0; i < 2; i++)
        #pragma unroll
        for (int j = 0; j < 4; j++) {
            const int r0 = m0 + wm + i * 16 + gid;
            const int c0 = n0 + wn + j * 8 + tig * 2;
            float2 v01 = make_float2(acc[i][j][0] * alpha, acc[i][j][1] * alpha);
            float2 v23 = make_float2(acc[i][j][2] * alpha, acc[i][j][3] * alpha);
            for (int r = 0; r < rep; r++) {
                *(float2*)&C[(size_t)r0 * N + c0 + (size_t)r * repStride] = v01;
                *(float2*)&C[(size_t)(r0 + 8) * N + c0 + (size_t)r * repStride] = v23;
            }
        }
}

// ---------------- softmax over rows of length 1024 ---------------------------
__global__ void softmax_rows(float* __restrict__ s)
{
    float* row = s + (size_t)blockIdx.x * SS;
    const int tid = threadIdx.x;
    __shared__ float red[256];
    float v[4];
    float m = -1e30f;
    #pragma unroll
    for (int i = 0; i < 4; i++) { v[i] = row[tid + i*256]; m = fmaxf(m, v[i]); }
    red[tid] = m; __syncthreads();
    for (int st = 128; st > 0; st >>= 1) {
        if (tid < st) red[tid] = fmaxf(red[tid], red[tid + st]);
        __syncthreads();
    }
    m = red[0]; __syncthreads();
    float sum = 0.f;
    #pragma unroll
    for (int i = 0; i < 4; i++) { v[i] = __expf(v[i] - m); sum += v[i]; }
    red[tid] = sum; __syncthreads();
    for (int st = 128; st > 0; st >>= 1) {
        if (tid < st) red[tid] += red[tid + st];
        __syncthreads();
    }
    const float inv = 1.f / red[0];
    #pragma unroll
    for (int i = 0; i < 4; i++) row[tid + i*256] = v[i] * inv;
}

// ---------------- y = a + (relu?)(b); partial column stats -------------------
__global__ void add_stats(const float* __restrict__ a, const float* __restrict__ b,
                          float* __restrict__ y, float* __restrict__ part, int relu)
{
    const int c = threadIdx.x;
    const int h = blockIdx.y;
    const int chunk = blockIdx.x;
    const size_t base = (size_t)h * BS * VV;
    float sum = 0.f, sq = 0.f;
    const int r0 = chunk * 128;
    for (int r = r0; r < r0 + 128; r++) {
        size_t idx = base + (size_t)r * VV + c;
        float bv = b[idx];
        if (relu) bv = fmaxf(bv, 0.f);
        float yv = a[idx] + bv;
        y[idx] = yv;
        sum += yv; sq += yv * yv;
    }
    size_t p = ((size_t)(h*NCH + chunk)*VV + c) * 2;
    part[p + 0] = sum;
    part[p + 1] = sq;
}

// ---------------- batchnorm normalize ---------------------------------------
__global__ void bn_norm(float* __restrict__ y, const float* __restrict__ part,
                        const float* __restrict__ gamma, const float* __restrict__ beta,
                        int gstride)
{
    const int c = threadIdx.x;
    const int h = blockIdx.y;
    const int chunk = blockIdx.x;
    const float* p = part + (size_t)h * NCH * VV * 2;
    float sum = 0.f, sq = 0.f;
    #pragma unroll
    for (int j = 0; j < NCH; j++) {
        sum += p[((size_t)j*VV + c)*2 + 0];
        sq  += p[((size_t)j*VV + c)*2 + 1];
    }
    const float mean = sum * (1.f / BS);
    const float var  = sq  * (1.f / BS) - mean * mean;
    const float inv  = rsqrtf(var + EPS);
    const float g = gamma[(size_t)h * gstride + c];
    const float b = beta [(size_t)h * gstride + c];
    const float sc = inv * g;
    const float sh = b - mean * sc;
    float* base = y + (size_t)h * BS * VV;
    const int r0 = chunk * 128;
    for (int r = r0; r < r0 + 128; r++) {
        size_t idx = (size_t)r * VV + c;
        base[idx] = base[idx] * sc + sh;
    }
}

// ---------------- [H][B*S][V] -> [B,S,H,V] -----------------------------------
__global__ void write_out(const float* __restrict__ net, float* __restrict__ out)
{
    const int h = blockIdx.y, row = blockIdx.x, c = threadIdx.x;
    out[((size_t)row * HH + h) * VV + c] =
        net[(size_t)h * BS * VV + (size_t)row * VV + c];
}

// ---------------- launcher ---------------------------------------------------
extern "C" void kernel_launch(void* const* d_in, const int* in_sizes, int n_in,
                              void* d_out, int out_size)
{
    const float* x     = (const float*)d_in[0];
    const float* W_in  = (const float*)d_in[1];
    const float* Wq    = (const float*)d_in[2];
    const float* Wk    = (const float*)d_in[3];
    const float* Wv    = (const float*)d_in[4];
    const float* Wd    = (const float*)d_in[5];
    const float* g1    = (const float*)d_in[6];
    const float* b1    = (const float*)d_in[7];
    const float* g2    = (const float*)d_in[8];
    const float* b2    = (const float*)d_in[9];
    float* out = (float*)d_out;

    float *net, *q, *k, *v, *scores, *attnout, *z, *part;
    cudaGetSymbolAddress((void**)&net,     g_net);
    cudaGetSymbolAddress((void**)&q,       g_q);
    cudaGetSymbolAddress((void**)&k,       g_k);
    cudaGetSymbolAddress((void**)&v,       g_v);
    cudaGetSymbolAddress((void**)&scores,  g_scores);
    cudaGetSymbolAddress((void**)&attnout, g_attnout);
    cudaGetSymbolAddress((void**)&z,       g_z);
    cudaGetSymbolAddress((void**)&part,    g_part);

    const int smem_bytes = SMEM_U32 * 4;   // 110592
    static int configured = 0;
    if (!configured) {
        cudaFuncSetAttribute(gemm_mma<0>, cudaFuncAttributeMaxDynamicSharedMemorySize, smem_bytes);
        cudaFuncSetAttribute(gemm_mma<1>, cudaFuncAttributeMaxDynamicSharedMemorySize, smem_bytes);
        configured = 1;
    }

    const float scale = 0.125f;   // KD^-0.5

    // net[h] = x @ W_in, replicated to all 8 heads
    gemm_mma<0><<<dim3(VV/GBN, BS/GBM, 1), 256, smem_bytes>>>(x, W_in, net, BS, VV, DIN,
                                                  0, 0, 0, 1.f, HH, (long long)BS*VV);

    for (int t = 0; t < TT; t++) {
        gemm_mma<0><<<dim3(KDIM/GBN, BS/GBM, HH), 256, smem_bytes>>>(net, Wq + (size_t)t*VV*KDIM, q,
            BS, KDIM, VV, (long long)BS*VV, (long long)TT*VV*KDIM, (long long)BS*KDIM, 1.f, 1, 0);
        gemm_mma<0><<<dim3(KDIM/GBN, BS/GBM, HH), 256, smem_bytes>>>(net, Wk + (size_t)t*VV*KDIM, k,
            BS, KDIM, VV, (long long)BS*VV, (long long)TT*VV*KDIM, (long long)BS*KDIM, 1.f, 1, 0);
        gemm_mma<0><<<dim3(VV/GBN, BS/GBM, HH), 256, smem_bytes>>>(net, Wv + (size_t)t*VV*VV, v,
            BS, VV, VV, (long long)BS*VV, (long long)TT*VV*VV, (long long)BS*VV, 1.f, 1, 0);

        // scores = scale * q @ k^T, batched over (h,b) = 32
        gemm_mma<1><<<dim3(SS/GBN, SS/GBM, HH*BB), 256, smem_bytes>>>(q, k, scores,
            SS, SS, KDIM, (long long)SS*KDIM, (long long)SS*KDIM, (long long)SS*SS, scale, 1, 0);

        softmax_rows<<<HH*BB*SS, 256>>>(scores);

        // attnout = scores @ v
        gemm_mma<0><<<dim3(VV/GBN, SS/GBM, HH*BB), 256, smem_bytes>>>(scores, v, attnout,
            SS, VV, SS, (long long)SS*SS, (long long)SS*VV, (long long)SS*VV, 1.f, 1, 0);

        // net = BN(net + attnout)
        add_stats<<<dim3(NCH, HH), 256>>>(net, attnout, net, part, 0);
        bn_norm<<<dim3(NCH, HH), 256>>>(net, part, g1 + (size_t)t*VV, b1 + (size_t)t*VV, TT*VV);

        // z = net @ Wd; net = BN(net + relu(z))
        gemm_mma<0><<<dim3(VV/GBN, BS/GBM, HH), 256, smem_bytes>>>(net, Wd + (size_t)t*VV*VV, z,
            BS, VV, VV, (long long)BS*VV, (long long)TT*VV*VV, (long long)BS*VV, 1.f, 1, 0);
        add_stats<<<dim3(NCH, HH), 256>>>(net, z, net, part, 1);
        bn_norm<<<dim3(NCH, HH), 256>>>(net, part, g2 + (size_t)t*VV, b2 + (size_t)t*VV, TT*VV);
    }

    write_out<<<dim3(BS, HH), 256>>>(net, out);
}

// round 8
// speedup vs baseline: 1.5220x; 1.0772x over previous
#include <cuda_runtime.h>
#include <cuda_bf16.h>
#include <math.h>

// Problem constants
#define BB   4
#define SS   1024
#define DIN  256
#define VV   256
#define KDIM 64
#define HH   8
#define TT   4
#define BS   (BB*SS)          // 4096
#define NCH  32               // stat chunks per head
#define EPS  1e-3f

// ---------------- scratch (device globals; no allocation allowed) -----------
__device__ float g_net[HH*BS*VV];
__device__ float g_q[HH*BS*KDIM];
__device__ float g_k[HH*BS*KDIM];
__device__ float g_v[HH*BS*VV];
__device__ float g_scores[(size_t)HH*BB*SS*SS];  // 134MB
__device__ float g_z[HH*BS*VV];
__device__ float g_part[HH*NCH*VV*2];

// ---------------- TF32 helpers ----------------------------------------------
__device__ __forceinline__ unsigned f2tf(float f) {
    unsigned r;
    asm("cvt.rna.tf32.f32 %0, %1;" : "=r"(r) : "f"(f));
    return r;
}

__device__ __forceinline__ void split_tf32(float f, unsigned &hi, unsigned &lo) {
    hi = f2tf(f);
    lo = f2tf(f - __uint_as_float(hi));
}

__device__ __forceinline__ void mma_tf32(float c[4],
                                         const unsigned a[4],
                                         const unsigned b[2]) {
    asm volatile(
        "mma.sync.aligned.m16n8k8.row.col.f32.tf32.tf32.f32 "
        "{%0,%1,%2,%3}, {%4,%5,%6,%7}, {%8,%9}, {%0,%1,%2,%3};"
        : "+f"(c[0]), "+f"(c[1]), "+f"(c[2]), "+f"(c[3])
        : "r"(a[0]), "r"(a[1]), "r"(a[2]), "r"(a[3]), "r"(b[0]), "r"(b[1]));
}

// ---------------- 3xTF32 tensor-core GEMM core (R5-proven) -------------------
// BM=128, BN=64, BK=32; 256 threads, 8 warps (4m x 2n), warp tile 32x32.
#define GBM 128
#define GBN 64
#define GBK 32
#define ASTR 36
#define BSTR_NN 72
#define BSTR_NT 36
#define A_TILE (GBM*ASTR)
#define B_TILE 2304
#define SMEM_U32 (2*A_TILE + 2*B_TILE)   // 13824 u32 = 55296 B

// EPI: 0 = plain C=alpha*acc (with rep); 1 = attnout fuse: y=R+acc, C=y, stats
//      (z->(h=z>>2,b=z&3), chunk=(z&3)*8+by); 2 = Wd fuse: y=R+relu(acc), C=y,
//      stats (h=z, chunk=by)
template<int NT, int EPI>
__global__ void __launch_bounds__(256)
gemm_mma(const float* __restrict__ A, const float* __restrict__ B,
         float* __restrict__ C, const float* __restrict__ R,
         float* __restrict__ part,
         int M, int N, int K,
         long long sA, long long sB, long long sC, long long sR,
         float alpha, int rep, long long repStride)
{
    A += (long long)blockIdx.z * sA;
    B += (long long)blockIdx.z * sB;
    C += (long long)blockIdx.z * sC;
    if (EPI) R += (long long)blockIdx.z * sR;

    extern __shared__ unsigned smem[];
    unsigned* AsH = smem;
    unsigned* AsL = smem + A_TILE;
    unsigned* BsH = smem + 2*A_TILE;
    unsigned* BsL = smem + 2*A_TILE + B_TILE;

    const int t    = threadIdx.x;
    const int lane = t & 31;
    const int wid  = t >> 5;
    const int gid  = lane >> 2;
    const int tig  = lane & 3;
    const int wm   = (wid & 3) * 32;
    const int wn   = (wid >> 2) * 32;
    const int m0 = blockIdx.y * GBM, n0 = blockIdx.x * GBN;

    float acc[2][4][4] = {};

    for (int k0 = 0; k0 < K; k0 += GBK) {
        float4 ar[4];
        #pragma unroll
        for (int i = 0; i < 4; i++) {
            int idx = t + i * 256;
            int r = idx >> 3, c4 = (idx & 7) << 2;
            ar[i] = *(const float4*)&A[(size_t)(m0 + r) * K + k0 + c4];
        }
        float4 br[2];
        #pragma unroll
        for (int i = 0; i < 2; i++) {
            int idx = t + i * 256;
            if (NT) {
                int r = idx >> 3, c4 = (idx & 7) << 2;
                br[i] = *(const float4*)&B[(size_t)(n0 + r) * K + k0 + c4];
            } else {
                int r = idx >> 4, c4 = (idx & 15) << 2;
                br[i] = *(const float4*)&B[(size_t)(k0 + r) * N + n0 + c4];
            }
        }
        __syncthreads();
        #pragma unroll
        for (int i = 0; i < 4; i++) {
            int idx = t + i * 256;
            int r = idx >> 3, c4 = (idx & 7) << 2;
            unsigned* ph = &AsH[r * ASTR + c4];
            unsigned* pl = &AsL[r * ASTR + c4];
            split_tf32(ar[i].x, ph[0], pl[0]);
            split_tf32(ar[i].y, ph[1], pl[1]);
            split_tf32(ar[i].z, ph[2], pl[2]);
            split_tf32(ar[i].w, ph[3], pl[3]);
        }
        #pragma unroll
        for (int i = 0; i < 2; i++) {
            int idx = t + i * 256;
            int off;
            if (NT) { int r = idx >> 3, c4 = (idx & 7) << 2;  off = r * BSTR_NT + c4; }
            else    { int r = idx >> 4, c4 = (idx & 15) << 2; off = r * BSTR_NN + c4; }
            unsigned* ph = &BsH[off];
            unsigned* pl = &BsL[off];
            split_tf32(br[i].x, ph[0], pl[0]);
            split_tf32(br[i].y, ph[1], pl[1]);
            split_tf32(br[i].z, ph[2], pl[2]);
            split_tf32(br[i].w, ph[3], pl[3]);
        }
        __syncthreads();

        #pragma unroll
        for (int ks = 0; ks < 4; ks++) {
            const int kk = ks * 8;
            unsigned aH[2][4], aL[2][4];
            #pragma unroll
            for (int i = 0; i < 2; i++) {
                const int mr = wm + i * 16;
                const int o0 = (mr + gid    ) * ASTR + kk + tig;
                const int o1 = (mr + gid + 8) * ASTR + kk + tig;
                aH[i][0] = AsH[o0];     aL[i][0] = AsL[o0];
                aH[i][1] = AsH[o1];     aL[i][1] = AsL[o1];
                aH[i][2] = AsH[o0 + 4]; aL[i][2] = AsL[o0 + 4];
                aH[i][3] = AsH[o1 + 4]; aL[i][3] = AsL[o1 + 4];
            }
            unsigned bH[4][2], bL[4][2];
            #pragma unroll
            for (int j = 0; j < 4; j++) {
                const int nc = wn + j * 8 + gid;
                int o0, o1;
                if (NT) { o0 = nc * BSTR_NT + kk + tig;  o1 = o0 + 4; }
                else    { o0 = (kk + tig) * BSTR_NN + nc; o1 = o0 + 4 * BSTR_NN; }
                bH[j][0] = BsH[o0]; bL[j][0] = BsL[o0];
                bH[j][1] = BsH[o1]; bL[j][1] = BsL[o1];
            }
            #pragma unroll
            for (int i = 0; i < 2; i++)
                #pragma unroll
                for (int j = 0; j < 4; j++) {
                    mma_tf32(acc[i][j], aL[i], bH[j]);
                    mma_tf32(acc[i][j], aH[i], bL[j]);
                    mma_tf32(acc[i][j], aH[i], bH[j]);
                }
        }
        __syncthreads();
    }

    if (EPI == 0) {
        #pragma unroll
        for (int i = 0; i < 2; i++)
            #pragma unroll
            for (int j = 0; j < 4; j++) {
                const int r0 = m0 + wm + i * 16 + gid;
                const int c0 = n0 + wn + j * 8 + tig * 2;
                float2 v01 = make_float2(acc[i][j][0] * alpha, acc[i][j][1] * alpha);
                float2 v23 = make_float2(acc[i][j][2] * alpha, acc[i][j][3] * alpha);
                for (int r = 0; r < rep; r++) {
                    *(float2*)&C[(size_t)r0 * N + c0 + (size_t)r * repStride] = v01;
                    *(float2*)&C[(size_t)(r0 + 8) * N + c0 + (size_t)r * repStride] = v23;
                }
            }
    } else {
        // y = R + (relu?)(acc); C = y; per-block column stats -> part
        float colsum[8] = {}, colsq[8] = {};
        #pragma unroll
        for (int i = 0; i < 2; i++)
            #pragma unroll
            for (int j = 0; j < 4; j++) {
                const int r0 = m0 + wm + i * 16 + gid;
                const int c0 = n0 + wn + j * 8 + tig * 2;
                float2 a0 = *(const float2*)&R[(size_t)r0 * N + c0];
                float2 a1 = *(const float2*)&R[(size_t)(r0 + 8) * N + c0];
                float v0 = acc[i][j][0], v1 = acc[i][j][1];
                float v2 = acc[i][j][2], v3 = acc[i][j][3];
                if (EPI == 2) {
                    v0 = fmaxf(v0, 0.f); v1 = fmaxf(v1, 0.f);
                    v2 = fmaxf(v2, 0.f); v3 = fmaxf(v3, 0.f);
                }
                float y00 = a0.x + v0, y01 = a0.y + v1;
                float y10 = a1.x + v2, y11 = a1.y + v3;
                *(float2*)&C[(size_t)r0 * N + c0]       = make_float2(y00, y01);
                *(float2*)&C[(size_t)(r0 + 8) * N + c0] = make_float2(y10, y11);
                colsum[j*2+0] += y00 + y10;
                colsum[j*2+1] += y01 + y11;
                colsq [j*2+0] += y00*y00 + y10*y10;
                colsq [j*2+1] += y01*y01 + y11*y11;
            }
        // reduce over gid (lanes differing in bits 2..4)
        #pragma unroll
        for (int c8 = 0; c8 < 8; c8++) {
            #pragma unroll
            for (int msk = 4; msk <= 16; msk <<= 1) {
                colsum[c8] += __shfl_xor_sync(0xffffffffu, colsum[c8], msk);
                colsq [c8] += __shfl_xor_sync(0xffffffffu, colsq [c8], msk);
            }
        }
        float* sred = (float*)smem;   // [4 m-warps][64 cols][2]
        if (gid == 0) {
            #pragma unroll
            for (int j = 0; j < 4; j++)
                #pragma unroll
                for (int e = 0; e < 2; e++) {
                    int col = wn + j * 8 + tig * 2 + e;
                    int idx = ((wid & 3) * 64 + col) * 2;
                    sred[idx + 0] = colsum[j*2+e];
                    sred[idx + 1] = colsq [j*2+e];
                }
        }
        __syncthreads();
        if (t < 64) {
            float s = 0.f, q2 = 0.f;
            #pragma unroll
            for (int w = 0; w < 4; w++) {
                s  += sred[(w * 64 + t) * 2 + 0];
                q2 += sred[(w * 64 + t) * 2 + 1];
            }
            int hh, chunk;
            if (EPI == 1) { hh = blockIdx.z >> 2; chunk = (blockIdx.z & 3) * 8 + blockIdx.y; }
            else          { hh = blockIdx.z;      chunk = blockIdx.y; }
            size_t p = ((size_t)(hh * NCH + chunk) * VV + (n0 + t)) * 2;
            part[p + 0] = s;
            part[p + 1] = q2;
        }
    }
}

// ---------------- fused q/k/v projection (one launch) ------------------------
// grid: (6, BS/GBM, HH). bx=0 -> q, bx=1 -> k, bx>=2 -> v col-block (bx-2).
__global__ void __launch_bounds__(256)
gemm_qkv(const float* __restrict__ net,
         const float* __restrict__ Wq_t, const float* __restrict__ Wk_t,
         const float* __restrict__ Wv_t,
         float* __restrict__ q, float* __restrict__ k, float* __restrict__ v)
{
    const int h = blockIdx.z;
    const int bx = blockIdx.x;
    const float* A = net + (size_t)h * BS * VV;
    const float* B;
    float* C;
    int N, n0;
    if (bx == 0)      { B = Wq_t + (size_t)h * TT * VV * KDIM; C = q + (size_t)h * BS * KDIM; N = KDIM; n0 = 0; }
    else if (bx == 1) { B = Wk_t + (size_t)h * TT * VV * KDIM; C = k + (size_t)h * BS * KDIM; N = KDIM; n0 = 0; }
    else              { B = Wv_t + (size_t)h * TT * VV * VV;   C = v + (size_t)h * BS * VV;   N = VV;   n0 = (bx - 2) * GBN; }
    const int K = VV;

    extern __shared__ unsigned smem[];
    unsigned* AsH = smem;
    unsigned* AsL = smem + A_TILE;
    unsigned* BsH = smem + 2*A_TILE;
    unsigned* BsL = smem + 2*A_TILE + B_TILE;

    const int t    = threadIdx.x;
    const int lane = t & 31;
    const int wid  = t >> 5;
    const int gid  = lane >> 2;
    const int tig  = lane & 3;
    const int wm   = (wid & 3) * 32;
    const int wn   = (wid >> 2) * 32;
    const int m0 = blockIdx.y * GBM;

    float acc[2][4][4] = {};

    for (int k0 = 0; k0 < K; k0 += GBK) {
        float4 ar[4];
        #pragma unroll
        for (int i = 0; i < 4; i++) {
            int idx = t + i * 256;
            int r = idx >> 3, c4 = (idx & 7) << 2;
            ar[i] = *(const float4*)&A[(size_t)(m0 + r) * K + k0 + c4];
        }
        float4 br[2];
        #pragma unroll
        for (int i = 0; i < 2; i++) {
            int idx = t + i * 256;
            int r = idx >> 4, c4 = (idx & 15) << 2;
            br[i] = *(const float4*)&B[(size_t)(k0 + r) * N + n0 + c4];
        }
        __syncthreads();
        #pragma unroll
        for (int i = 0; i < 4; i++) {
            int idx = t + i * 256;
            int r = idx >> 3, c4 = (idx & 7) << 2;
            unsigned* ph = &AsH[r * ASTR + c4];
            unsigned* pl = &AsL[r * ASTR + c4];
            split_tf32(ar[i].x, ph[0], pl[0]);
            split_tf32(ar[i].y, ph[1], pl[1]);
            split_tf32(ar[i].z, ph[2], pl[2]);
            split_tf32(ar[i].w, ph[3], pl[3]);
        }
        #pragma unroll
        for (int i = 0; i < 2; i++) {
            int idx = t + i * 256;
            int r = idx >> 4, c4 = (idx & 15) << 2;
            int off = r * BSTR_NN + c4;
            unsigned* ph = &BsH[off];
            unsigned* pl = &BsL[off];
            split_tf32(br[i].x, ph[0], pl[0]);
            split_tf32(br[i].y, ph[1], pl[1]);
            split_tf32(br[i].z, ph[2], pl[2]);
            split_tf32(br[i].w, ph[3], pl[3]);
        }
        __syncthreads();

        #pragma unroll
        for (int ks = 0; ks < 4; ks++) {
            const int kk = ks * 8;
            unsigned aH[2][4], aL[2][4];
            #pragma unroll
            for (int i = 0; i < 2; i++) {
                const int mr = wm + i * 16;
                const int o0 = (mr + gid    ) * ASTR + kk + tig;
                const int o1 = (mr + gid + 8) * ASTR + kk + tig;
                aH[i][0] = AsH[o0];     aL[i][0] = AsL[o0];
                aH[i][1] = AsH[o1];     aL[i][1] = AsL[o1];
                aH[i][2] = AsH[o0 + 4]; aL[i][2] = AsL[o0 + 4];
                aH[i][3] = AsH[o1 + 4]; aL[i][3] = AsL[o1 + 4];
            }
            unsigned bH[4][2], bL[4][2];
            #pragma unroll
            for (int j = 0; j < 4; j++) {
                const int nc = wn + j * 8 + gid;
                int o0 = (kk + tig) * BSTR_NN + nc;
                int o1 = o0 + 4 * BSTR_NN;
                bH[j][0] = BsH[o0]; bL[j][0] = BsL[o0];
                bH[j][1] = BsH[o1]; bL[j][1] = BsL[o1];
            }
            #pragma unroll
            for (int i = 0; i < 2; i++)
                #pragma unroll
                for (int j = 0; j < 4; j++) {
                    mma_tf32(acc[i][j], aL[i], bH[j]);
                    mma_tf32(acc[i][j], aH[i], bL[j]);
                    mma_tf32(acc[i][j], aH[i], bH[j]);
                }
        }
        __syncthreads();
    }

    #pragma unroll
    for (int i = 0; i < 2; i++)
        #pragma unroll
        for (int j = 0; j < 4; j++) {
            const int r0 = m0 + wm + i * 16 + gid;
            const int c0 = n0 + wn + j * 8 + tig * 2;
            *(float2*)&C[(size_t)r0 * N + c0] =
                make_float2(acc[i][j][0], acc[i][j][1]);
            *(float2*)&C[(size_t)(r0 + 8) * N + c0] =
                make_float2(acc[i][j][2], acc[i][j][3]);
        }
}

// ---------------- softmax over rows of length 1024 ---------------------------
__global__ void softmax_rows(float* __restrict__ s)
{
    float* row = s + (size_t)blockIdx.x * SS;
    const int tid = threadIdx.x;
    __shared__ float red[256];
    float v[4];
    float m = -1e30f;
    #pragma unroll
    for (int i = 0; i < 4; i++) { v[i] = row[tid + i*256]; m = fmaxf(m, v[i]); }
    red[tid] = m; __syncthreads();
    for (int st = 128; st > 0; st >>= 1) {
        if (tid < st) red[tid] = fmaxf(red[tid], red[tid + st]);
        __syncthreads();
    }
    m = red[0]; __syncthreads();
    float sum = 0.f;
    #pragma unroll
    for (int i = 0; i < 4; i++) { v[i] = __expf(v[i] - m); sum += v[i]; }
    red[tid] = sum; __syncthreads();
    for (int st = 128; st > 0; st >>= 1) {
        if (tid < st) red[tid] += red[tid + st];
        __syncthreads();
    }
    const float inv = 1.f / red[0];
    #pragma unroll
    for (int i = 0; i < 4; i++) row[tid + i*256] = v[i] * inv;
}

// ---------------- batchnorm normalize: dst = norm(src) -----------------------
__global__ void bn_norm(const float* __restrict__ src, float* __restrict__ dst,
                        const float* __restrict__ part,
                        const float* __restrict__ gamma, const float* __restrict__ beta,
                        int gstride)
{
    const int c = threadIdx.x;
    const int h = blockIdx.y;
    const int chunk = blockIdx.x;
    const float* p = part + (size_t)h * NCH * VV * 2;
    float sum = 0.f, sq = 0.f;
    #pragma unroll
    for (int j = 0; j < NCH; j++) {
        sum += p[((size_t)j*VV + c)*2 + 0];
        sq  += p[((size_t)j*VV + c)*2 + 1];
    }
    const float mean = sum * (1.f / BS);
    const float var  = sq  * (1.f / BS) - mean * mean;
    const float inv  = rsqrtf(var + EPS);
    const float g = gamma[(size_t)h * gstride + c];
    const float b = beta [(size_t)h * gstride + c];
    const float sc = inv * g;
    const float sh = b - mean * sc;
    const float* sbase = src + (size_t)h * BS * VV;
    float*       dbase = dst + (size_t)h * BS * VV;
    const int r0 = chunk * 128;
    for (int r = r0; r < r0 + 128; r++) {
        size_t idx = (size_t)r * VV + c;
        dbase[idx] = sbase[idx] * sc + sh;
    }
}

// ---------------- [H][B*S][V] -> [B,S,H,V] -----------------------------------
__global__ void write_out(const float* __restrict__ net, float* __restrict__ out)
{
    const int h = blockIdx.y, row = blockIdx.x, c = threadIdx.x;
    out[((size_t)row * HH + h) * VV + c] =
        net[(size_t)h * BS * VV + (size_t)row * VV + c];
}

// ---------------- launcher ---------------------------------------------------
extern "C" void kernel_launch(void* const* d_in, const int* in_sizes, int n_in,
                              void* d_out, int out_size)
{
    const float* x     = (const float*)d_in[0];
    const float* W_in  = (const float*)d_in[1];
    const float* Wq    = (const float*)d_in[2];
    const float* Wk    = (const float*)d_in[3];
    const float* Wv    = (const float*)d_in[4];
    const float* Wd    = (const float*)d_in[5];
    const float* g1    = (const float*)d_in[6];
    const float* b1    = (const float*)d_in[7];
    const float* g2    = (const float*)d_in[8];
    const float* b2    = (const float*)d_in[9];
    float* out = (float*)d_out;

    float *net, *q, *k, *v, *scores, *z, *part;
    cudaGetSymbolAddress((void**)&net,    g_net);
    cudaGetSymbolAddress((void**)&q,      g_q);
    cudaGetSymbolAddress((void**)&k,      g_k);
    cudaGetSymbolAddress((void**)&v,      g_v);
    cudaGetSymbolAddress((void**)&scores, g_scores);
    cudaGetSymbolAddress((void**)&z,      g_z);
    cudaGetSymbolAddress((void**)&part,   g_part);

    const int smem_bytes = SMEM_U32 * 4;   // 55296
    static int configured = 0;
    if (!configured) {
        cudaFuncSetAttribute(gemm_mma<0,0>, cudaFuncAttributeMaxDynamicSharedMemorySize, smem_bytes);
        cudaFuncSetAttribute(gemm_mma<1,0>, cudaFuncAttributeMaxDynamicSharedMemorySize, smem_bytes);
        cudaFuncSetAttribute(gemm_mma<0,1>, cudaFuncAttributeMaxDynamicSharedMemorySize, smem_bytes);
        cudaFuncSetAttribute(gemm_mma<0,2>, cudaFuncAttributeMaxDynamicSharedMemorySize, smem_bytes);
        cudaFuncSetAttribute(gemm_qkv,      cudaFuncAttributeMaxDynamicSharedMemorySize, smem_bytes);
        configured = 1;
    }

    const float scale = 0.125f;   // KD^-0.5

    // net[h] = x @ W_in, replicated to all 8 heads
    gemm_mma<0,0><<<dim3(VV/GBN, BS/GBM, 1), 256, smem_bytes>>>(
        x, W_in, net, nullptr, nullptr, BS, VV, DIN,
        0, 0, 0, 0, 1.f, HH, (long long)BS*VV);

    for (int t = 0; t < TT; t++) {
        // q, k, v in one launch
        gemm_qkv<<<dim3(6, BS/GBM, HH), 256, smem_bytes>>>(
            net, Wq + (size_t)t*VV*KDIM, Wk + (size_t)t*VV*KDIM,
            Wv + (size_t)t*VV*VV, q, k, v);

        // scores = scale * q @ k^T, batched over (h,b) = 32
        gemm_mma<1,0><<<dim3(SS/GBN, SS/GBM, HH*BB), 256, smem_bytes>>>(
            q, k, scores, nullptr, nullptr, SS, SS, KDIM,
            (long long)SS*KDIM, (long long)SS*KDIM, (long long)SS*SS, 0,
            scale, 1, 0);

        softmax_rows<<<HH*BB*SS, 256>>>(scores);

        // net = net + scores @ v (in-place residual) + BN partial stats
        gemm_mma<0,1><<<dim3(VV/GBN, SS/GBM, HH*BB), 256, smem_bytes>>>(
            scores, v, net, net, part, SS, VV, SS,
            (long long)SS*SS, (long long)SS*VV, (long long)SS*VV, (long long)SS*VV,
            1.f, 1, 0);
        bn_norm<<<dim3(NCH, HH), 256>>>(net, net, part,
            g1 + (size_t)t*VV, b1 + (size_t)t*VV, TT*VV);

        // z = net + relu(net @ Wd) + BN partial stats; net = BN(z)
        gemm_mma<0,2><<<dim3(VV/GBN, BS/GBM, HH), 256, smem_bytes>>>(
            net, Wd + (size_t)t*VV*VV, z, net, part, BS, VV, VV,
            (long long)BS*VV, (long long)TT*VV*VV, (long long)BS*VV, (long long)BS*VV,
            1.f, 1, 0);
        bn_norm<<<dim3(NCH, HH), 256>>>(z, net, part,
            g2 + (size_t)t*VV, b2 + (size_t)t*VV, TT*VV);
    }

    write_out<<<dim3(BS, HH), 256>>>(net, out);
}